// round 1
// baseline (speedup 1.0000x reference)
#include <cuda_runtime.h>
#include <cstdint>

#define H 1024
#define SEQ 512
#define VOCAB 50257

// output layout: [log_softmax(VOCAB) | h(H) | c(H) | attn_weights(SEQ)]
#define OUT_LOGITS 0
#define OUT_H      (VOCAB)
#define OUT_C      (VOCAB + H)
#define OUT_AW     (VOCAB + 2 * H)

// ---------------- device scratch (no allocations allowed) ----------------
__device__ float g_attn_logits[SEQ];
__device__ float g_attn_w[SEQ];
__device__ float g_attn_applied[H];
__device__ float g_x[H];
__device__ float g_gates[4 * H];
__device__ float g_h[H];
__device__ float g_c[H];
__device__ float g_pmax[128];
__device__ float g_psum[128];
__device__ float g_lse;

__device__ __forceinline__ float dot4(float4 a, float4 b) {
    return a.x * b.x + a.y * b.y + a.z * b.z + a.w * b.w;
}

__device__ __forceinline__ float block_reduce_sum(float v, float* sdata) {
    int t = threadIdx.x;
    sdata[t] = v;
    __syncthreads();
    for (int s = blockDim.x >> 1; s > 0; s >>= 1) {
        if (t < s) sdata[t] += sdata[t + s];
        __syncthreads();
    }
    return sdata[0];
}

__device__ __forceinline__ float sigmoidf(float x) {
    return 1.0f / (1.0f + expf(-x));
}

// ---------------- 1. attention scores: [emb_row, h0] @ attn_W.T + attn_b ----------------
__global__ void attn_score_kernel(const int* __restrict__ idx,
                                  const float* __restrict__ emb,
                                  const float* __restrict__ h0,
                                  const float* __restrict__ attn_W,
                                  const float* __restrict__ attn_b) {
    __shared__ float sdata[256];
    int s = blockIdx.x;              // 0..SEQ-1
    int t = threadIdx.x;             // 256 threads
    int row = idx[0];
    const float4* w = (const float4*)(attn_W + (size_t)s * (2 * H));
    const float4* e = (const float4*)(emb + (size_t)row * H);
    const float4* h = (const float4*)h0;
    float acc = 0.0f;
    // 2*H floats = 512 float4; first 256 from embedded, next 256 from h0
    for (int i = t; i < 512; i += 256) {
        float4 in = (i < 256) ? e[i] : h[i - 256];
        acc += dot4(in, w[i]);
    }
    float sum = block_reduce_sum(acc, sdata);
    if (t == 0) g_attn_logits[s] = sum + attn_b[s];
}

// ---------------- 2. softmax over SEQ ----------------
__global__ void softmax_kernel(float* __restrict__ out) {
    __shared__ float sdata[SEQ];
    int t = threadIdx.x;             // 512 threads
    float v = g_attn_logits[t];
    sdata[t] = v;
    __syncthreads();
    for (int s = SEQ >> 1; s > 0; s >>= 1) {
        if (t < s) sdata[t] = fmaxf(sdata[t], sdata[t + s]);
        __syncthreads();
    }
    float m = sdata[0];
    __syncthreads();
    float e = expf(v - m);
    sdata[t] = e;
    __syncthreads();
    for (int s = SEQ >> 1; s > 0; s >>= 1) {
        if (t < s) sdata[t] += sdata[t + s];
        __syncthreads();
    }
    float w = e / sdata[0];
    g_attn_w[t] = w;
    out[OUT_AW + t] = w;
}

// ---------------- 3. attn_applied = attn_w @ encoder_outputs ----------------
__global__ void attn_applied_kernel(const float* __restrict__ enc) {
    int j = blockIdx.x * blockDim.x + threadIdx.x;   // 0..H-1
    if (j >= H) return;
    float acc = 0.0f;
#pragma unroll 8
    for (int s = 0; s < SEQ; s++) {
        acc += g_attn_w[s] * enc[(size_t)s * H + j];
    }
    g_attn_applied[j] = acc;
}

// ---------------- 4. x = relu([emb_row, attn_applied] @ comb_W.T + comb_b) ----------------
__global__ void comb_kernel(const int* __restrict__ idx,
                            const float* __restrict__ emb,
                            const float* __restrict__ comb_W,
                            const float* __restrict__ comb_b) {
    __shared__ float sdata[256];
    int r = blockIdx.x;              // 0..H-1
    int t = threadIdx.x;             // 256 threads
    int row = idx[0];
    const float4* w = (const float4*)(comb_W + (size_t)r * (2 * H));
    const float4* e = (const float4*)(emb + (size_t)row * H);
    const float4* a = (const float4*)g_attn_applied;
    float acc = 0.0f;
    for (int i = t; i < 512; i += 256) {
        float4 in = (i < 256) ? e[i] : a[i - 256];
        acc += dot4(in, w[i]);
    }
    float sum = block_reduce_sum(acc, sdata);
    if (t == 0) g_x[r] = fmaxf(sum + comb_b[r], 0.0f);
}

// ---------------- 5. gates = x @ w_ih.T + b_ih + h0 @ w_hh.T + b_hh ----------------
__global__ void gates_kernel(const float* __restrict__ h0,
                             const float* __restrict__ w_ih,
                             const float* __restrict__ w_hh,
                             const float* __restrict__ b_ih,
                             const float* __restrict__ b_hh) {
    __shared__ float sdata[256];
    int r = blockIdx.x;              // 0..4H-1
    int t = threadIdx.x;             // 256 threads; H floats = 256 float4 each
    const float4* wi = (const float4*)(w_ih + (size_t)r * H);
    const float4* wh = (const float4*)(w_hh + (size_t)r * H);
    const float4* x4 = (const float4*)g_x;
    const float4* h4 = (const float4*)h0;
    float acc = dot4(x4[t], wi[t]) + dot4(h4[t], wh[t]);
    float sum = block_reduce_sum(acc, sdata);
    if (t == 0) g_gates[r] = sum + b_ih[r] + b_hh[r];
}

// ---------------- 6. LSTM elementwise ----------------
__global__ void lstm_kernel(const float* __restrict__ c0, float* __restrict__ out) {
    int j = blockIdx.x * blockDim.x + threadIdx.x;
    if (j >= H) return;
    float i = sigmoidf(g_gates[j]);
    float f = sigmoidf(g_gates[H + j]);
    float g = tanhf(g_gates[2 * H + j]);
    float o = sigmoidf(g_gates[3 * H + j]);
    float c = f * c0[j] + i * g;
    float h = o * tanhf(c);
    g_c[j] = c;
    g_h[j] = h;
    out[OUT_H + j] = h;
    out[OUT_C + j] = c;
}

// ---------------- 7. logits = h @ out_W.T + out_b (raw, into d_out) ----------------
__global__ void logits_kernel(const float* __restrict__ out_W,
                              const float* __restrict__ out_b,
                              float* __restrict__ out) {
    __shared__ float sdata[128];
    int r = blockIdx.x;              // 0..VOCAB-1
    int t = threadIdx.x;             // 128 threads
    const float4* w = (const float4*)(out_W + (size_t)r * H);
    const float4* h4 = (const float4*)g_h;
    // H floats = 256 float4; 128 threads -> 2 each
    float acc = dot4(h4[t], w[t]) + dot4(h4[t + 128], w[t + 128]);
    float sum = block_reduce_sum(acc, sdata);
    if (t == 0) out[OUT_LOGITS + r] = sum + out_b[r];
}

// ---------------- 8. log-sum-exp pass 1: 128 block partials (online) ----------------
__device__ __forceinline__ void combine_ms(float& m, float& s, float m2, float s2) {
    float M = fmaxf(m, m2);
    s = s * expf(m - M) + s2 * expf(m2 - M);
    m = M;
}

__global__ void lse_partial_kernel(const float* __restrict__ out) {
    __shared__ float sm[256];
    __shared__ float ss[256];
    int t = threadIdx.x;
    int gid = blockIdx.x * 256 + t;
    const int stride = 128 * 256;
    float m = -1e30f, s = 0.0f;
    for (int i = gid; i < VOCAB; i += stride) {
        float x = out[i];
        if (x > m) { s = s * expf(m - x) + 1.0f; m = x; }
        else       { s += expf(x - m); }
    }
    sm[t] = m; ss[t] = s;
    __syncthreads();
    for (int k = 128; k > 0; k >>= 1) {
        if (t < k) {
            float m2 = sm[t + k], s2 = ss[t + k];
            float M = fmaxf(sm[t], m2);
            ss[t] = ss[t] * expf(sm[t] - M) + s2 * expf(m2 - M);
            sm[t] = M;
        }
        __syncthreads();
    }
    if (t == 0) { g_pmax[blockIdx.x] = sm[0]; g_psum[blockIdx.x] = ss[0]; }
}

// ---------------- 9. log-sum-exp pass 2: combine 128 partials ----------------
__global__ void lse_final_kernel() {
    __shared__ float sm[128];
    __shared__ float ss[128];
    int t = threadIdx.x;             // 128 threads
    sm[t] = g_pmax[t];
    ss[t] = g_psum[t];
    __syncthreads();
    for (int k = 64; k > 0; k >>= 1) {
        if (t < k) {
            float m2 = sm[t + k], s2 = ss[t + k];
            float M = fmaxf(sm[t], m2);
            ss[t] = ss[t] * expf(sm[t] - M) + s2 * expf(m2 - M);
            sm[t] = M;
        }
        __syncthreads();
    }
    if (t == 0) g_lse = sm[0] + logf(ss[0]);
}

// ---------------- 10. subtract lse ----------------
__global__ void sub_lse_kernel(float* __restrict__ out) {
    int i = blockIdx.x * blockDim.x + threadIdx.x;
    if (i < VOCAB) out[i] -= g_lse;
}

extern "C" void kernel_launch(void* const* d_in, const int* in_sizes, int n_in,
                              void* d_out, int out_size) {
    const int*   idx     = (const int*)  d_in[0];
    const float* h0      = (const float*)d_in[1];
    const float* c0      = (const float*)d_in[2];
    const float* enc     = (const float*)d_in[3];
    const float* emb     = (const float*)d_in[4];
    const float* attn_W  = (const float*)d_in[5];
    const float* attn_b  = (const float*)d_in[6];
    const float* comb_W  = (const float*)d_in[7];
    const float* comb_b  = (const float*)d_in[8];
    const float* w_ih    = (const float*)d_in[9];
    const float* w_hh    = (const float*)d_in[10];
    const float* b_ih    = (const float*)d_in[11];
    const float* b_hh    = (const float*)d_in[12];
    const float* out_W   = (const float*)d_in[13];
    const float* out_b   = (const float*)d_in[14];
    float* out = (float*)d_out;

    attn_score_kernel<<<SEQ, 256>>>(idx, emb, h0, attn_W, attn_b);
    softmax_kernel<<<1, SEQ>>>(out);
    attn_applied_kernel<<<H / 256, 256>>>(enc);
    comb_kernel<<<H, 256>>>(idx, emb, comb_W, comb_b);
    gates_kernel<<<4 * H, 256>>>(h0, w_ih, w_hh, b_ih, b_hh);
    lstm_kernel<<<H / 256, 256>>>(c0, out);
    logits_kernel<<<VOCAB, 128>>>(out_W, out_b, out);
    lse_partial_kernel<<<128, 256>>>(out);
    lse_final_kernel<<<1, 128>>>();
    sub_lse_kernel<<<(VOCAB + 255) / 256, 256>>>(out);
}

// round 2
// speedup vs baseline: 1.5649x; 1.5649x over previous
#include <cuda_runtime.h>
#include <cstdint>

#define H 1024
#define SEQ 512
#define VOCAB 50257

// output layout: [log_softmax(VOCAB) | h(H) | c(H) | attn_weights(SEQ)]
#define OUT_LOGITS 0
#define OUT_H      (VOCAB)
#define OUT_C      (VOCAB + H)
#define OUT_AW     (VOCAB + 2 * H)

// ---------------- device scratch ----------------
__device__ float g_attn_logits[SEQ];
__device__ float g_attn_w[SEQ];
__device__ float g_attn_applied[H];
__device__ float g_x[H];
__device__ float g_h[H];
__device__ float g_pmax[128];
__device__ float g_psum[128];

__device__ __forceinline__ float dot4(float4 a, float4 b) {
    return a.x * b.x + a.y * b.y + a.z * b.z + a.w * b.w;
}

__device__ __forceinline__ float warp_sum(float v) {
#pragma unroll
    for (int o = 16; o > 0; o >>= 1) v += __shfl_down_sync(0xffffffffu, v, o);
    return v;
}

__device__ __forceinline__ float sigmoidf_(float x) {
    return 1.0f / (1.0f + expf(-x));
}

// ---- 1. attention scores: warp per row, 512 rows x 2048 floats ----
__global__ void attn_score_kernel(const int* __restrict__ idx,
                                  const float* __restrict__ emb,
                                  const float* __restrict__ h0,
                                  const float* __restrict__ attn_W,
                                  const float* __restrict__ attn_b) {
    int warp = threadIdx.x >> 5;
    int lane = threadIdx.x & 31;
    int r = blockIdx.x * 8 + warp;            // 0..SEQ-1 (grid = 64)
    int row = idx[0];
    const float4* w  = (const float4*)(attn_W + (size_t)r * (2 * H));
    const float4* e4 = (const float4*)(emb + (size_t)row * H);
    const float4* h4 = (const float4*)h0;
    float acc = 0.0f;
#pragma unroll
    for (int k = 0; k < 16; k++) {
        int i = lane + 32 * k;                // 0..511
        float4 in = (i < 256) ? e4[i] : h4[i - 256];
        acc += dot4(in, w[i]);
    }
    acc = warp_sum(acc);
    if (lane == 0) g_attn_logits[r] = acc + attn_b[r];
}

// ---- 2. softmax over SEQ (single block) + zero attn_applied accumulator ----
__global__ void softmax_kernel(float* __restrict__ out) {
    __shared__ float sdata[SEQ];
    int t = threadIdx.x;                      // 512 threads
    // zero the atomic accumulator for attn_applied
    g_attn_applied[t] = 0.0f;
    g_attn_applied[t + 512] = 0.0f;
    float v = g_attn_logits[t];
    sdata[t] = v;
    __syncthreads();
    for (int s = SEQ >> 1; s > 0; s >>= 1) {
        if (t < s) sdata[t] = fmaxf(sdata[t], sdata[t + s]);
        __syncthreads();
    }
    float m = sdata[0];
    __syncthreads();
    float e = expf(v - m);
    sdata[t] = e;
    __syncthreads();
    for (int s = SEQ >> 1; s > 0; s >>= 1) {
        if (t < s) sdata[t] += sdata[t + s];
        __syncthreads();
    }
    float w = e / sdata[0];
    g_attn_w[t] = w;
    out[OUT_AW + t] = w;
}

// ---- 3. attn_applied = attn_w @ encoder_outputs (16 row-chunks, atomic combine) ----
__global__ void attn_applied_kernel(const float* __restrict__ enc) {
    int t = threadIdx.x;                      // 256 threads: one float4 column each
    int r0 = blockIdx.x * 32;                 // 16 blocks x 32 rows
    const float4* e4 = (const float4*)enc;
    float4 acc = make_float4(0.f, 0.f, 0.f, 0.f);
#pragma unroll 8
    for (int s = 0; s < 32; s++) {
        float w = g_attn_w[r0 + s];
        float4 v = e4[(size_t)(r0 + s) * 256 + t];
        acc.x += w * v.x; acc.y += w * v.y; acc.z += w * v.z; acc.w += w * v.w;
    }
    atomicAdd(&g_attn_applied[4 * t + 0], acc.x);
    atomicAdd(&g_attn_applied[4 * t + 1], acc.y);
    atomicAdd(&g_attn_applied[4 * t + 2], acc.z);
    atomicAdd(&g_attn_applied[4 * t + 3], acc.w);
}

// ---- 4. x = relu([emb_row, attn_applied] @ comb_W.T + comb_b): warp per row ----
__global__ void comb_kernel(const int* __restrict__ idx,
                            const float* __restrict__ emb,
                            const float* __restrict__ comb_W,
                            const float* __restrict__ comb_b) {
    int warp = threadIdx.x >> 5;
    int lane = threadIdx.x & 31;
    int r = blockIdx.x * 8 + warp;            // 0..H-1 (grid = 128)
    int row = idx[0];
    const float4* w  = (const float4*)(comb_W + (size_t)r * (2 * H));
    const float4* e4 = (const float4*)(emb + (size_t)row * H);
    const float4* a4 = (const float4*)g_attn_applied;
    float acc = 0.0f;
#pragma unroll
    for (int k = 0; k < 16; k++) {
        int i = lane + 32 * k;
        float4 in = (i < 256) ? e4[i] : a4[i - 256];
        acc += dot4(in, w[i]);
    }
    acc = warp_sum(acc);
    if (lane == 0) g_x[r] = fmaxf(acc + comb_b[r], 0.0f);
}

// ---- 5. gates + LSTM fused: block j computes all 4 gate rows, warp per gate ----
__global__ void gates_lstm_kernel(const float* __restrict__ h0,
                                  const float* __restrict__ c0,
                                  const float* __restrict__ w_ih,
                                  const float* __restrict__ w_hh,
                                  const float* __restrict__ b_ih,
                                  const float* __restrict__ b_hh,
                                  float* __restrict__ out) {
    __shared__ float sgate[4];
    int j = blockIdx.x;                       // 0..H-1
    int warp = threadIdx.x >> 5;              // gate index 0..3 (128 threads)
    int lane = threadIdx.x & 31;
    int r = warp * H + j;                     // gate row
    const float4* wi = (const float4*)(w_ih + (size_t)r * H);
    const float4* wh = (const float4*)(w_hh + (size_t)r * H);
    const float4* x4 = (const float4*)g_x;
    const float4* h4 = (const float4*)h0;
    float acc = 0.0f;
#pragma unroll
    for (int k = 0; k < 8; k++) {
        int i = lane + 32 * k;                // 0..255
        acc += dot4(x4[i], wi[i]);
        acc += dot4(h4[i], wh[i]);
    }
    acc = warp_sum(acc);
    if (lane == 0) sgate[warp] = acc + b_ih[r] + b_hh[r];
    __syncthreads();
    if (threadIdx.x == 0) {
        float i = sigmoidf_(sgate[0]);
        float f = sigmoidf_(sgate[1]);
        float g = tanhf(sgate[2]);
        float o = sigmoidf_(sgate[3]);
        float c = f * c0[j] + i * g;
        float h = o * tanhf(c);
        g_h[j] = h;
        out[OUT_H + j] = h;
        out[OUT_C + j] = c;
    }
}

// ---- 6. logits = h @ out_W.T + out_b : warp per row, h cached in smem ----
__global__ void __launch_bounds__(256) logits_kernel(const float* __restrict__ out_W,
                              const float* __restrict__ out_b,
                              float* __restrict__ out) {
    __shared__ float4 sh[256];
    int t = threadIdx.x;
    sh[t] = ((const float4*)g_h)[t];
    __syncthreads();
    int warp = t >> 5;
    int lane = t & 31;
    int r = blockIdx.x * 8 + warp;            // grid = 6283
    if (r >= VOCAB) return;
    const float4* w = (const float4*)(out_W + (size_t)r * H);
    float acc = 0.0f;
#pragma unroll
    for (int k = 0; k < 8; k++) {
        int i = lane + 32 * k;                // 0..255
        acc += dot4(sh[i], w[i]);
    }
    acc = warp_sum(acc);
    if (lane == 0) out[OUT_LOGITS + r] = acc + out_b[r];
}

// ---- 7. log-sum-exp pass 1: 128 block partials (online) ----
__global__ void lse_partial_kernel(const float* __restrict__ out) {
    __shared__ float sm[256];
    __shared__ float ss[256];
    int t = threadIdx.x;
    int gid = blockIdx.x * 256 + t;
    const int stride = 128 * 256;
    float m = -1e30f, s = 0.0f;
    for (int i = gid; i < VOCAB; i += stride) {
        float x = out[i];
        if (x > m) { s = s * expf(m - x) + 1.0f; m = x; }
        else       { s += expf(x - m); }
    }
    sm[t] = m; ss[t] = s;
    __syncthreads();
    for (int k = 128; k > 0; k >>= 1) {
        if (t < k) {
            float m2 = sm[t + k], s2 = ss[t + k];
            float M = fmaxf(sm[t], m2);
            ss[t] = ss[t] * expf(sm[t] - M) + s2 * expf(m2 - M);
            sm[t] = M;
        }
        __syncthreads();
    }
    if (t == 0) { g_pmax[blockIdx.x] = sm[0]; g_psum[blockIdx.x] = ss[0]; }
}

// ---- 8. combine partials (per block) + subtract lse ----
__global__ void sub_lse_kernel(float* __restrict__ out) {
    __shared__ float sm[128];
    __shared__ float ss[128];
    __shared__ float s_lse;
    int t = threadIdx.x;                      // 256 threads
    if (t < 128) { sm[t] = g_pmax[t]; ss[t] = g_psum[t]; }
    __syncthreads();
    for (int k = 64; k > 0; k >>= 1) {
        if (t < k) {
            float m2 = sm[t + k], s2 = ss[t + k];
            float M = fmaxf(sm[t], m2);
            ss[t] = ss[t] * expf(sm[t] - M) + s2 * expf(m2 - M);
            sm[t] = M;
        }
        __syncthreads();
    }
    if (t == 0) s_lse = sm[0] + logf(ss[0]);
    __syncthreads();
    float lse = s_lse;
    int base = blockIdx.x * 1024;             // 4 elements per thread, grid = 50
#pragma unroll
    for (int k = 0; k < 4; k++) {
        int i = base + t + 256 * k;
        if (i < VOCAB) out[i] -= lse;
    }
}

extern "C" void kernel_launch(void* const* d_in, const int* in_sizes, int n_in,
                              void* d_out, int out_size) {
    const int*   idx     = (const int*)  d_in[0];
    const float* h0      = (const float*)d_in[1];
    const float* c0      = (const float*)d_in[2];
    const float* enc     = (const float*)d_in[3];
    const float* emb     = (const float*)d_in[4];
    const float* attn_W  = (const float*)d_in[5];
    const float* attn_b  = (const float*)d_in[6];
    const float* comb_W  = (const float*)d_in[7];
    const float* comb_b  = (const float*)d_in[8];
    const float* w_ih    = (const float*)d_in[9];
    const float* w_hh    = (const float*)d_in[10];
    const float* b_ih    = (const float*)d_in[11];
    const float* b_hh    = (const float*)d_in[12];
    const float* out_W   = (const float*)d_in[13];
    const float* out_b   = (const float*)d_in[14];
    float* out = (float*)d_out;

    attn_score_kernel<<<SEQ / 8, 256>>>(idx, emb, h0, attn_W, attn_b);
    softmax_kernel<<<1, SEQ>>>(out);
    attn_applied_kernel<<<16, 256>>>(enc);
    comb_kernel<<<H / 8, 256>>>(idx, emb, comb_W, comb_b);
    gates_lstm_kernel<<<H, 128>>>(h0, c0, w_ih, w_hh, b_ih, b_hh, out);
    logits_kernel<<<(VOCAB + 7) / 8, 256>>>(out_W, out_b, out);
    lse_partial_kernel<<<128, 256>>>(out);
    sub_lse_kernel<<<(VOCAB + 1023) / 1024, 256>>>(out);
}